// round 4
// baseline (speedup 1.0000x reference)
#include <cuda_runtime.h>

// Shapes: x [8,16,4,8192,2] f32; psi_hat [24,16384,2]; phi_hat [1,16384,2];
// idx [32,2] int32 OR int64 (JAX x64-default ambiguity — sniffed at runtime);
// out [8,32,4,8192,2] f32.
#define N_FFT    16384
#define T_LEN    8192
#define NTHREADS 512
#define NB       (N_FFT / 4)                 // butterflies per radix-4 stage
// Bank-conflict-avoiding padded smem index: one extra float2 per 16.
#define P(i) ((i) + ((i) >> 4))
#define SMEM_F2    (N_FFT + N_FFT / 16)      // 17408 float2
#define SMEM_BYTES (SMEM_F2 * 8)             // 139264 bytes

__device__ float2 g_tw[N_FFT / 4];           // exp(-2*pi*i*k/N), k < N/4
__device__ float2 g_xhat[512 * N_FFT];       // forward FFT results, 64 MiB
__device__ float2 g_filtrev[26 * N_FFT];     // digit-reversed filter spectra
__device__ int    g_idx[64];                 // normalized (jr, f) pairs

__device__ __forceinline__ float2 cmul(float2 a, float2 b) {
    return make_float2(fmaf(a.x, b.x, -a.y * b.y), fmaf(a.x, b.y, a.y * b.x));
}

__device__ __forceinline__ int digitrev4(int v) {
    int r = 0;
#pragma unroll
    for (int i = 0; i < 7; i++) { r = (r << 2) | (v & 3); v >>= 2; }
    return r;
}

__global__ void tw_init_kernel() {
    int k = blockIdx.x * blockDim.x + threadIdx.x;
    if (k < N_FFT / 4) {
        double s, c;
        sincospi(-2.0 * (double)k / (double)N_FFT, &s, &c);
        g_tw[k] = make_float2((float)c, (float)s);
    }
}

// Normalize idx regardless of int32/int64 storage.
// int64 little-endian viewed as int32 words: [v0,0, v1,0, ...] -> the 32 odd
// words (high halves, values in [0,16)) are ALL zero. int32 layout: odd words
// are idx[:,1] (random in [0,16)) -> all-zero essentially impossible.
// Reading words [0,64) = 256 bytes is in-bounds under both layouts.
__global__ void idx_norm_kernel(const int* __restrict__ raw) {
    __shared__ int nz;
    int tid = threadIdx.x;
    if (tid == 0) nz = 0;
    __syncthreads();
    if (tid < 32 && raw[2 * tid + 1] != 0) atomicOr(&nz, 1);
    __syncthreads();
    if (tid < 64) {
        int v = nz ? raw[tid]            // int32 layout: word tid is element tid
                   : raw[2 * tid];       // int64 layout: low word of element tid
        // jr (even slots) used mod 16 table; f (odd slots) addresses 26 rows.
        g_idx[tid] = min(max(v, 0), (tid & 1) ? 25 : 15);
    }
}

// Pre-permute the 26 filter spectra (24 psi + phi + phi) into radix-4
// digit-reversed order so inverse-FFT CTAs read them coalesced.
__global__ void filt_prep_kernel(const float* __restrict__ psi,
                                 const float* __restrict__ phi) {
    int p = blockIdx.x * blockDim.x + threadIdx.x;
    int row = p >> 14;
    if (row >= 26) return;
    int q = p & (N_FFT - 1);
    int src = digitrev4(q);
    const float* f = (row < 24) ? (psi + (size_t)row * N_FFT * 2) : phi;
    g_filtrev[p] = make_float2(f[2 * src], f[2 * src + 1]);
}

// Forward: reflection-pad + in-place radix-4 DIF (natural in -> digit-reversed out)
__global__ void __launch_bounds__(NTHREADS)
fwd_fft_kernel(const float* __restrict__ x) {
    extern __shared__ float2 sm[];
    const int seq = blockIdx.x;                 // ((c*16 + jr)*4 + a), 0..511
    const float2* xi = (const float2*)(x + (size_t)seq * T_LEN * 2);
    const int tid = threadIdx.x;

    for (int t = tid; t < T_LEN; t += NTHREADS) {
        float2 v = xi[t];
        sm[P(t)] = v;
        sm[P(2 * T_LEN - 1 - t)] = v;           // reflection pad
    }
    __syncthreads();

#pragma unroll
    for (int s = 0; s < 7; s++) {
        const int l2 = 12 - 2 * s;
        const int L  = 1 << l2;
#pragma unroll
        for (int it = 0; it < NB / NTHREADS; it++) {
            int t = tid + it * NTHREADS;
            int j = t & (L - 1);
            int base = ((t >> l2) << (l2 + 2)) + j;
            float2 a0 = sm[P(base)],         a1 = sm[P(base + L)];
            float2 a2 = sm[P(base + 2 * L)], a3 = sm[P(base + 3 * L)];
            float2 w1 = g_tw[j << (2 * s)];
            float2 w2 = cmul(w1, w1);
            float2 w3 = cmul(w2, w1);
            float2 t0 = make_float2(a0.x + a2.x, a0.y + a2.y);
            float2 t1 = make_float2(a0.x - a2.x, a0.y - a2.y);
            float2 t2 = make_float2(a1.x + a3.x, a1.y + a3.y);
            float2 t3 = make_float2(a1.x - a3.x, a1.y - a3.y);
            float2 y0 = make_float2(t0.x + t2.x, t0.y + t2.y);
            float2 y2 = make_float2(t0.x - t2.x, t0.y - t2.y);
            float2 y1 = make_float2(t1.x + t3.y, t1.y - t3.x);   // t1 - i*t3
            float2 y3 = make_float2(t1.x - t3.y, t1.y + t3.x);   // t1 + i*t3
            sm[P(base)]         = y0;
            sm[P(base + L)]     = cmul(y1, w1);
            sm[P(base + 2 * L)] = cmul(y2, w2);
            sm[P(base + 3 * L)] = cmul(y3, w3);
        }
        __syncthreads();
    }

    float2* out = g_xhat + (size_t)seq * N_FFT;
    for (int t = tid; t < N_FFT; t += NTHREADS) out[t] = sm[P(t)];
}

// Inverse: gather + pointwise multiply (digit-reversed domain) + radix-4 DIT
// that exactly inverts the DIF pass, scale 1/N, write first T samples.
__global__ void __launch_bounds__(NTHREADS)
inv_fft_kernel(float* __restrict__ out) {
    extern __shared__ float2 sm[];
    const int b  = blockIdx.x;                  // ((c*32 + cj)*4 + a), 0..1023
    const int a  = b & 3;
    const int cj = (b >> 2) & 31;
    const int c  = b >> 7;
    const int jr = g_idx[2 * cj];
    const int f  = g_idx[2 * cj + 1];
    const float2* xh = g_xhat    + (size_t)((c * 16 + jr) * 4 + a) * N_FFT;
    const float2* fr = g_filtrev + (size_t)f * N_FFT;
    const int tid = threadIdx.x;

    for (int t = tid; t < N_FFT; t += NTHREADS)
        sm[P(t)] = cmul(xh[t], fr[t]);
    __syncthreads();

#pragma unroll
    for (int s = 6; s >= 0; s--) {
        const int l2 = 12 - 2 * s;
        const int L  = 1 << l2;
#pragma unroll
        for (int it = 0; it < NB / NTHREADS; it++) {
            int t = tid + it * NTHREADS;
            int j = t & (L - 1);
            int base = ((t >> l2) << (l2 + 2)) + j;
            float2 w1 = g_tw[j << (2 * s)];
            w1.y = -w1.y;                        // conjugate -> inverse twiddle
            float2 w2 = cmul(w1, w1);
            float2 w3 = cmul(w2, w1);
            float2 b0 = sm[P(base)];
            float2 b1 = cmul(sm[P(base + L)],     w1);
            float2 b2 = cmul(sm[P(base + 2 * L)], w2);
            float2 b3 = cmul(sm[P(base + 3 * L)], w3);
            float2 t0 = make_float2(b0.x + b2.x, b0.y + b2.y);
            float2 t1 = make_float2(b0.x - b2.x, b0.y - b2.y);
            float2 t2 = make_float2(b1.x + b3.x, b1.y + b3.y);
            float2 t3 = make_float2(b1.x - b3.x, b1.y - b3.y);
            sm[P(base)]         = make_float2(t0.x + t2.x, t0.y + t2.y);
            sm[P(base + 2 * L)] = make_float2(t0.x - t2.x, t0.y - t2.y);
            sm[P(base + L)]     = make_float2(t1.x - t3.y, t1.y + t3.x); // t1 + i*t3
            sm[P(base + 3 * L)] = make_float2(t1.x + t3.y, t1.y - t3.x); // t1 - i*t3
        }
        __syncthreads();
    }

    float2* o = (float2*)(out + (size_t)b * T_LEN * 2);
    const float scale = 1.0f / (float)N_FFT;
    for (int t = tid; t < T_LEN; t += NTHREADS) {
        float2 v = sm[P(t)];
        o[t] = make_float2(v.x * scale, v.y * scale);
    }
}

extern "C" void kernel_launch(void* const* d_in, const int* in_sizes, int n_in,
                              void* d_out, int out_size) {
    const float* x   = (const float*)d_in[0];
    const float* psi = (const float*)d_in[1];
    const float* phi = (const float*)d_in[2];
    const int* idxr  = (const int*)d_in[3];
    float* out       = (float*)d_out;

    cudaFuncSetAttribute(fwd_fft_kernel,
                         cudaFuncAttributeMaxDynamicSharedMemorySize, SMEM_BYTES);
    cudaFuncSetAttribute(inv_fft_kernel,
                         cudaFuncAttributeMaxDynamicSharedMemorySize, SMEM_BYTES);

    tw_init_kernel<<<(N_FFT / 4 + 511) / 512, 512>>>();
    idx_norm_kernel<<<1, 64>>>(idxr);
    filt_prep_kernel<<<(26 * N_FFT + 511) / 512, 512>>>(psi, phi);
    fwd_fft_kernel<<<512, NTHREADS, SMEM_BYTES>>>(x);
    inv_fft_kernel<<<1024, NTHREADS, SMEM_BYTES>>>(out);
}

// round 5
// speedup vs baseline: 1.2696x; 1.2696x over previous
#include <cuda_runtime.h>

// Shapes: x [8,16,4,8192,2] f32; psi_hat [24,16384,2]; phi_hat [1,16384,2];
// idx [32,2] int32 (sniffed, tolerates int64); out [8,32,4,8192,2] f32.
#define N_FFT    16384
#define T_LEN    8192
#define NTHREADS 512
// Bank-conflict-avoiding padded smem index: one extra float2 per 16.
#define P(i) ((i) + ((i) >> 4))
#define SMEM_F2    (N_FFT + N_FFT / 16)      // 17408 float2
#define SMEM_BYTES (SMEM_F2 * 8)             // 139264 bytes

__device__ float2 g_tw[N_FFT / 4];           // exp(-2*pi*i*k/N), k < N/4
__device__ float2 g_xhat[512 * N_FFT];       // forward FFT results, 64 MiB
__device__ float2 g_filtrev[26 * N_FFT];     // digit-reversed filter spectra
__device__ int    g_idx[64];                 // normalized (jr, f) pairs

__device__ __forceinline__ float2 cmul(float2 a, float2 b) {
    return make_float2(fmaf(a.x, b.x, -a.y * b.y), fmaf(a.x, b.y, a.y * b.x));
}

// Forward (DIF) radix-4 butterfly; twiddles multiply the outputs.
__device__ __forceinline__ void bfly4_dif(float2& x0, float2& x1, float2& x2,
                                          float2& x3, float2 w1) {
    float2 w2 = cmul(w1, w1);
    float2 w3 = cmul(w2, w1);
    float2 t0 = make_float2(x0.x + x2.x, x0.y + x2.y);
    float2 t1 = make_float2(x0.x - x2.x, x0.y - x2.y);
    float2 t2 = make_float2(x1.x + x3.x, x1.y + x3.y);
    float2 t3 = make_float2(x1.x - x3.x, x1.y - x3.y);
    x0 = make_float2(t0.x + t2.x, t0.y + t2.y);
    float2 y1 = make_float2(t1.x + t3.y, t1.y - t3.x);   // t1 - i*t3
    float2 y2 = make_float2(t0.x - t2.x, t0.y - t2.y);
    float2 y3 = make_float2(t1.x - t3.y, t1.y + t3.x);   // t1 + i*t3
    x1 = cmul(y1, w1);
    x2 = cmul(y2, w2);
    x3 = cmul(y3, w3);
}

__device__ __forceinline__ void bfly4_dif_nw(float2& x0, float2& x1,
                                             float2& x2, float2& x3) {
    float2 t0 = make_float2(x0.x + x2.x, x0.y + x2.y);
    float2 t1 = make_float2(x0.x - x2.x, x0.y - x2.y);
    float2 t2 = make_float2(x1.x + x3.x, x1.y + x3.y);
    float2 t3 = make_float2(x1.x - x3.x, x1.y - x3.y);
    x0 = make_float2(t0.x + t2.x, t0.y + t2.y);
    x1 = make_float2(t1.x + t3.y, t1.y - t3.x);
    x2 = make_float2(t0.x - t2.x, t0.y - t2.y);
    x3 = make_float2(t1.x - t3.y, t1.y + t3.x);
}

// Inverse (DIT) radix-4 butterfly; w1c is already conjugated, applied to inputs.
__device__ __forceinline__ void bfly4_dit(float2& x0, float2& x1, float2& x2,
                                          float2& x3, float2 w1c) {
    float2 w2 = cmul(w1c, w1c);
    float2 w3 = cmul(w2, w1c);
    float2 b1 = cmul(x1, w1c);
    float2 b2 = cmul(x2, w2);
    float2 b3 = cmul(x3, w3);
    float2 t0 = make_float2(x0.x + b2.x, x0.y + b2.y);
    float2 t1 = make_float2(x0.x - b2.x, x0.y - b2.y);
    float2 t2 = make_float2(b1.x + b3.x, b1.y + b3.y);
    float2 t3 = make_float2(b1.x - b3.x, b1.y - b3.y);
    x0 = make_float2(t0.x + t2.x, t0.y + t2.y);
    x1 = make_float2(t1.x - t3.y, t1.y + t3.x);          // t1 + i*t3
    x2 = make_float2(t0.x - t2.x, t0.y - t2.y);
    x3 = make_float2(t1.x + t3.y, t1.y - t3.x);          // t1 - i*t3
}

__device__ __forceinline__ void bfly4_dit_nw(float2& x0, float2& x1,
                                             float2& x2, float2& x3) {
    float2 t0 = make_float2(x0.x + x2.x, x0.y + x2.y);
    float2 t1 = make_float2(x0.x - x2.x, x0.y - x2.y);
    float2 t2 = make_float2(x1.x + x3.x, x1.y + x3.y);
    float2 t3 = make_float2(x1.x - x3.x, x1.y - x3.y);
    x0 = make_float2(t0.x + t2.x, t0.y + t2.y);
    x1 = make_float2(t1.x - t3.y, t1.y + t3.x);
    x2 = make_float2(t0.x - t2.x, t0.y - t2.y);
    x3 = make_float2(t1.x + t3.y, t1.y - t3.x);
}

// Fused pair of DIF stages (s, s+1) done in registers: each thread handles
// two 16-point units (4x4 grid: base + m*L4 + q*L). One smem round-trip.
template <int S>
__device__ __forceinline__ void fwd_fused_phase(float2* sm, int tid) {
    constexpr int l2 = 12 - 2 * S;
    constexpr int L  = 1 << l2;
    constexpr int L4 = L >> 2;
#pragma unroll
    for (int u = 0; u < 2; u++) {
        int v = tid + u * NTHREADS;                // unit id, 0..1023
        int block = v >> (l2 - 2);
        int j0 = v & (L4 - 1);
        int base = (block << (l2 + 2)) + j0;
        float2 d[4][4];
#pragma unroll
        for (int m = 0; m < 4; m++)
#pragma unroll
            for (int q = 0; q < 4; q++)
                d[m][q] = sm[P(base + m * L4 + q * L)];
        // stage S: butterfly across q for each m
#pragma unroll
        for (int m = 0; m < 4; m++) {
            float2 w1 = g_tw[(j0 + m * L4) << (2 * S)];
            bfly4_dif(d[m][0], d[m][1], d[m][2], d[m][3], w1);
        }
        // stage S+1: butterfly across m for each q (same twiddle for all q)
        float2 w1b = g_tw[j0 << (2 * S + 2)];
#pragma unroll
        for (int q = 0; q < 4; q++)
            bfly4_dif(d[0][q], d[1][q], d[2][q], d[3][q], w1b);
#pragma unroll
        for (int m = 0; m < 4; m++)
#pragma unroll
            for (int q = 0; q < 4; q++)
                sm[P(base + m * L4 + q * L)] = d[m][q];
    }
    __syncthreads();
}

// Exact inverse of fwd_fused_phase<S>: stage S+1 first, then stage S,
// with conjugated twiddles.
template <int S>
__device__ __forceinline__ void inv_fused_phase(float2* sm, int tid) {
    constexpr int l2 = 12 - 2 * S;
    constexpr int L  = 1 << l2;
    constexpr int L4 = L >> 2;
#pragma unroll
    for (int u = 0; u < 2; u++) {
        int v = tid + u * NTHREADS;
        int block = v >> (l2 - 2);
        int j0 = v & (L4 - 1);
        int base = (block << (l2 + 2)) + j0;
        float2 d[4][4];
#pragma unroll
        for (int m = 0; m < 4; m++)
#pragma unroll
            for (int q = 0; q < 4; q++)
                d[m][q] = sm[P(base + m * L4 + q * L)];
        // stage S+1 inverse: across m for each q
        float2 w1b = g_tw[j0 << (2 * S + 2)];
        w1b.y = -w1b.y;
#pragma unroll
        for (int q = 0; q < 4; q++)
            bfly4_dit(d[0][q], d[1][q], d[2][q], d[3][q], w1b);
        // stage S inverse: across q for each m
#pragma unroll
        for (int m = 0; m < 4; m++) {
            float2 w1 = g_tw[(j0 + m * L4) << (2 * S)];
            w1.y = -w1.y;
            bfly4_dit(d[m][0], d[m][1], d[m][2], d[m][3], w1);
        }
#pragma unroll
        for (int m = 0; m < 4; m++)
#pragma unroll
            for (int q = 0; q < 4; q++)
                sm[P(base + m * L4 + q * L)] = d[m][q];
    }
    __syncthreads();
}

__device__ __forceinline__ int digitrev4(int v) {
    int r = 0;
#pragma unroll
    for (int i = 0; i < 7; i++) { r = (r << 2) | (v & 3); v >>= 2; }
    return r;
}

__global__ void tw_init_kernel() {
    int k = blockIdx.x * blockDim.x + threadIdx.x;
    if (k < N_FFT / 4) {
        double s, c;
        sincospi(-2.0 * (double)k / (double)N_FFT, &s, &c);
        g_tw[k] = make_float2((float)c, (float)s);
    }
}

// Normalize idx regardless of int32/int64 storage (layout sniff; see R2-R4).
__global__ void idx_norm_kernel(const int* __restrict__ raw) {
    __shared__ int nz;
    int tid = threadIdx.x;
    if (tid == 0) nz = 0;
    __syncthreads();
    if (tid < 32 && raw[2 * tid + 1] != 0) atomicOr(&nz, 1);
    __syncthreads();
    if (tid < 64) {
        int v = nz ? raw[tid] : raw[2 * tid];
        g_idx[tid] = min(max(v, 0), (tid & 1) ? 25 : 15);
    }
}

// Pre-permute the 26 filter spectra (24 psi + phi + phi) into radix-4
// digit-reversed order so inverse-FFT CTAs read them coalesced.
__global__ void filt_prep_kernel(const float* __restrict__ psi,
                                 const float* __restrict__ phi) {
    int p = blockIdx.x * blockDim.x + threadIdx.x;
    int row = p >> 14;
    if (row >= 26) return;
    int q = p & (N_FFT - 1);
    int src = digitrev4(q);
    const float* f = (row < 24) ? (psi + (size_t)row * N_FFT * 2) : phi;
    g_filtrev[p] = make_float2(f[2 * src], f[2 * src + 1]);
}

// Forward: reflection-pad + radix-4 DIF as 3 fused radix-16 phases + 1 final
// twiddle-free stage. Natural in -> digit-reversed out.
__global__ void __launch_bounds__(NTHREADS)
fwd_fft_kernel(const float* __restrict__ x) {
    extern __shared__ float2 sm[];
    const int seq = blockIdx.x;                 // ((c*16 + jr)*4 + a), 0..511
    const float2* xi = (const float2*)(x + (size_t)seq * T_LEN * 2);
    const int tid = threadIdx.x;

    for (int t = tid; t < T_LEN; t += NTHREADS) {
        float2 v = xi[t];
        sm[P(t)] = v;
        sm[P(2 * T_LEN - 1 - t)] = v;           // reflection pad
    }
    __syncthreads();

    fwd_fused_phase<0>(sm, tid);                // stages 0,1 (L=4096,1024)
    fwd_fused_phase<2>(sm, tid);                // stages 2,3 (L=256,64)
    fwd_fused_phase<4>(sm, tid);                // stages 4,5 (L=16,4)

    // final stage s=6 (L=1): j=0 -> all twiddles are 1
#pragma unroll
    for (int it = 0; it < 8; it++) {
        int t = tid + it * NTHREADS;            // 4096 butterflies
        int base = 4 * t;
        float2 a0 = sm[P(base)],     a1 = sm[P(base + 1)];
        float2 a2 = sm[P(base + 2)], a3 = sm[P(base + 3)];
        bfly4_dif_nw(a0, a1, a2, a3);
        sm[P(base)] = a0;     sm[P(base + 1)] = a1;
        sm[P(base + 2)] = a2; sm[P(base + 3)] = a3;
    }
    __syncthreads();

    float2* out = g_xhat + (size_t)seq * N_FFT;
    for (int t = tid; t < N_FFT; t += NTHREADS) out[t] = sm[P(t)];
}

// Inverse: gather + multiply (digit-reversed domain) + mirrored DIT phases,
// scale 1/N, write first T samples.
__global__ void __launch_bounds__(NTHREADS)
inv_fft_kernel(float* __restrict__ out) {
    extern __shared__ float2 sm[];
    const int b  = blockIdx.x;                  // ((c*32 + cj)*4 + a), 0..1023
    const int a  = b & 3;
    const int cj = (b >> 2) & 31;
    const int c  = b >> 7;
    const int jr = g_idx[2 * cj];
    const int f  = g_idx[2 * cj + 1];
    const float2* xh = g_xhat    + (size_t)((c * 16 + jr) * 4 + a) * N_FFT;
    const float2* fr = g_filtrev + (size_t)f * N_FFT;
    const int tid = threadIdx.x;

    for (int t = tid; t < N_FFT; t += NTHREADS)
        sm[P(t)] = cmul(xh[t], fr[t]);
    __syncthreads();

    // stage s=6 first (L=1, twiddle-free)
#pragma unroll
    for (int it = 0; it < 8; it++) {
        int t = tid + it * NTHREADS;
        int base = 4 * t;
        float2 a0 = sm[P(base)],     a1 = sm[P(base + 1)];
        float2 a2 = sm[P(base + 2)], a3 = sm[P(base + 3)];
        bfly4_dit_nw(a0, a1, a2, a3);
        sm[P(base)] = a0;     sm[P(base + 1)] = a1;
        sm[P(base + 2)] = a2; sm[P(base + 3)] = a3;
    }
    __syncthreads();

    inv_fused_phase<4>(sm, tid);                // stages 5,4
    inv_fused_phase<2>(sm, tid);                // stages 3,2
    inv_fused_phase<0>(sm, tid);                // stages 1,0

    float2* o = (float2*)(out + (size_t)b * T_LEN * 2);
    const float scale = 1.0f / (float)N_FFT;
    for (int t = tid; t < T_LEN; t += NTHREADS) {
        float2 v = sm[P(t)];
        o[t] = make_float2(v.x * scale, v.y * scale);
    }
}

extern "C" void kernel_launch(void* const* d_in, const int* in_sizes, int n_in,
                              void* d_out, int out_size) {
    const float* x   = (const float*)d_in[0];
    const float* psi = (const float*)d_in[1];
    const float* phi = (const float*)d_in[2];
    const int* idxr  = (const int*)d_in[3];
    float* out       = (float*)d_out;

    cudaFuncSetAttribute(fwd_fft_kernel,
                         cudaFuncAttributeMaxDynamicSharedMemorySize, SMEM_BYTES);
    cudaFuncSetAttribute(inv_fft_kernel,
                         cudaFuncAttributeMaxDynamicSharedMemorySize, SMEM_BYTES);

    tw_init_kernel<<<(N_FFT / 4 + 511) / 512, 512>>>();
    idx_norm_kernel<<<1, 64>>>(idxr);
    filt_prep_kernel<<<(26 * N_FFT + 511) / 512, 512>>>(psi, phi);
    fwd_fft_kernel<<<512, NTHREADS, SMEM_BYTES>>>(x);
    inv_fft_kernel<<<1024, NTHREADS, SMEM_BYTES>>>(out);
}

// round 6
// speedup vs baseline: 1.4608x; 1.1506x over previous
#include <cuda_runtime.h>

// Shapes: x [8,16,4,8192,2] f32; psi_hat [24,16384,2]; phi_hat [1,16384,2];
// idx [32,2] int32 (sniffed, tolerates int64); out [8,32,4,8192,2] f32.
#define N_FFT    16384
#define T_LEN    8192
#define NT       1024
// Bank-conflict-avoiding padded smem index: one extra float2 per 16.
#define P(i) ((i) + ((i) >> 4))
#define SMEM_F2    (N_FFT + N_FFT / 16)      // 17408 float2
#define SMEM_BYTES (SMEM_F2 * 8)             // 139264 bytes

__device__ __align__(16) float2 g_tw[N_FFT / 4];
__device__ __align__(16) float2 g_xhat[512 * N_FFT];     // 64 MiB
__device__ __align__(16) float2 g_filtrev[26 * N_FFT];   // digit-reversed filters
__device__ int g_idx[64];

__device__ __forceinline__ float2 cmul(float2 a, float2 b) {
    return make_float2(fmaf(a.x, b.x, -a.y * b.y), fmaf(a.x, b.y, a.y * b.x));
}

// Forward (DIF) radix-4 butterfly; twiddles multiply outputs.
__device__ __forceinline__ void bfly4_dif(float2& x0, float2& x1, float2& x2,
                                          float2& x3, float2 w1) {
    float2 w2 = cmul(w1, w1);
    float2 w3 = cmul(w2, w1);
    float2 t0 = make_float2(x0.x + x2.x, x0.y + x2.y);
    float2 t1 = make_float2(x0.x - x2.x, x0.y - x2.y);
    float2 t2 = make_float2(x1.x + x3.x, x1.y + x3.y);
    float2 t3 = make_float2(x1.x - x3.x, x1.y - x3.y);
    x0 = make_float2(t0.x + t2.x, t0.y + t2.y);
    float2 y1 = make_float2(t1.x + t3.y, t1.y - t3.x);   // t1 - i*t3
    float2 y2 = make_float2(t0.x - t2.x, t0.y - t2.y);
    float2 y3 = make_float2(t1.x - t3.y, t1.y + t3.x);   // t1 + i*t3
    x1 = cmul(y1, w1);
    x2 = cmul(y2, w2);
    x3 = cmul(y3, w3);
}

__device__ __forceinline__ void bfly4_dif_nw(float2& x0, float2& x1,
                                             float2& x2, float2& x3) {
    float2 t0 = make_float2(x0.x + x2.x, x0.y + x2.y);
    float2 t1 = make_float2(x0.x - x2.x, x0.y - x2.y);
    float2 t2 = make_float2(x1.x + x3.x, x1.y + x3.y);
    float2 t3 = make_float2(x1.x - x3.x, x1.y - x3.y);
    x0 = make_float2(t0.x + t2.x, t0.y + t2.y);
    x1 = make_float2(t1.x + t3.y, t1.y - t3.x);
    x2 = make_float2(t0.x - t2.x, t0.y - t2.y);
    x3 = make_float2(t1.x - t3.y, t1.y + t3.x);
}

// Inverse (DIT) radix-4; w1c already conjugated, applied to inputs.
__device__ __forceinline__ void bfly4_dit(float2& x0, float2& x1, float2& x2,
                                          float2& x3, float2 w1c) {
    float2 w2 = cmul(w1c, w1c);
    float2 w3 = cmul(w2, w1c);
    float2 b1 = cmul(x1, w1c);
    float2 b2 = cmul(x2, w2);
    float2 b3 = cmul(x3, w3);
    float2 t0 = make_float2(x0.x + b2.x, x0.y + b2.y);
    float2 t1 = make_float2(x0.x - b2.x, x0.y - b2.y);
    float2 t2 = make_float2(b1.x + b3.x, b1.y + b3.y);
    float2 t3 = make_float2(b1.x - b3.x, b1.y - b3.y);
    x0 = make_float2(t0.x + t2.x, t0.y + t2.y);
    x1 = make_float2(t1.x - t3.y, t1.y + t3.x);          // t1 + i*t3
    x2 = make_float2(t0.x - t2.x, t0.y - t2.y);
    x3 = make_float2(t1.x + t3.y, t1.y - t3.x);          // t1 - i*t3
}

__device__ __forceinline__ void bfly4_dit_nw(float2& x0, float2& x1,
                                             float2& x2, float2& x3) {
    float2 t0 = make_float2(x0.x + x2.x, x0.y + x2.y);
    float2 t1 = make_float2(x0.x - x2.x, x0.y - x2.y);
    float2 t2 = make_float2(x1.x + x3.x, x1.y + x3.y);
    float2 t3 = make_float2(x1.x - x3.x, x1.y - x3.y);
    x0 = make_float2(t0.x + t2.x, t0.y + t2.y);
    x1 = make_float2(t1.x - t3.y, t1.y + t3.x);
    x2 = make_float2(t0.x - t2.x, t0.y - t2.y);
    x3 = make_float2(t1.x + t3.y, t1.y - t3.x);
}

// Fused DIF stage pair (S, S+1), one 16-point unit per thread, smem->smem.
template <int S>
__device__ __forceinline__ void fwd_fused_phase(float2* sm, int v) {
    constexpr int l2 = 12 - 2 * S;
    constexpr int L  = 1 << l2;
    constexpr int L4 = L >> 2;
    int block = v >> (l2 - 2);
    int j0 = v & (L4 - 1);
    int base = (block << (l2 + 2)) + j0;
    float2 d[4][4];
#pragma unroll
    for (int m = 0; m < 4; m++)
#pragma unroll
        for (int q = 0; q < 4; q++)
            d[m][q] = sm[P(base + m * L4 + q * L)];
#pragma unroll
    for (int m = 0; m < 4; m++)
        bfly4_dif(d[m][0], d[m][1], d[m][2], d[m][3],
                  g_tw[(j0 + m * L4) << (2 * S)]);
    float2 w1b = g_tw[j0 << (2 * S + 2)];
#pragma unroll
    for (int q = 0; q < 4; q++)
        bfly4_dif(d[0][q], d[1][q], d[2][q], d[3][q], w1b);
#pragma unroll
    for (int m = 0; m < 4; m++)
#pragma unroll
        for (int q = 0; q < 4; q++)
            sm[P(base + m * L4 + q * L)] = d[m][q];
    __syncthreads();
}

// Exact inverse of fwd_fused_phase<S>: stage S+1 then S, conjugated twiddles.
template <int S>
__device__ __forceinline__ void inv_fused_phase(float2* sm, int v) {
    constexpr int l2 = 12 - 2 * S;
    constexpr int L  = 1 << l2;
    constexpr int L4 = L >> 2;
    int block = v >> (l2 - 2);
    int j0 = v & (L4 - 1);
    int base = (block << (l2 + 2)) + j0;
    float2 d[4][4];
#pragma unroll
    for (int m = 0; m < 4; m++)
#pragma unroll
        for (int q = 0; q < 4; q++)
            d[m][q] = sm[P(base + m * L4 + q * L)];
    float2 w1b = g_tw[j0 << (2 * S + 2)];
    w1b.y = -w1b.y;
#pragma unroll
    for (int q = 0; q < 4; q++)
        bfly4_dit(d[0][q], d[1][q], d[2][q], d[3][q], w1b);
#pragma unroll
    for (int m = 0; m < 4; m++) {
        float2 w1 = g_tw[(j0 + m * L4) << (2 * S)];
        w1.y = -w1.y;
        bfly4_dit(d[m][0], d[m][1], d[m][2], d[m][3], w1);
    }
#pragma unroll
    for (int m = 0; m < 4; m++)
#pragma unroll
        for (int q = 0; q < 4; q++)
            sm[P(base + m * L4 + q * L)] = d[m][q];
    __syncthreads();
}

__device__ __forceinline__ int digitrev4(int v) {
    int r = 0;
#pragma unroll
    for (int i = 0; i < 7; i++) { r = (r << 2) | (v & 3); v >>= 2; }
    return r;
}

__global__ void tw_init_kernel() {
    int k = blockIdx.x * blockDim.x + threadIdx.x;
    if (k < N_FFT / 4) {
        double s, c;
        sincospi(-2.0 * (double)k / (double)N_FFT, &s, &c);
        g_tw[k] = make_float2((float)c, (float)s);
    }
}

// Normalize idx regardless of int32/int64 storage (layout sniff, see R2-R4).
__global__ void idx_norm_kernel(const int* __restrict__ raw) {
    __shared__ int nz;
    int tid = threadIdx.x;
    if (tid == 0) nz = 0;
    __syncthreads();
    if (tid < 32 && raw[2 * tid + 1] != 0) atomicOr(&nz, 1);
    __syncthreads();
    if (tid < 64) {
        int v = nz ? raw[tid] : raw[2 * tid];
        g_idx[tid] = min(max(v, 0), (tid & 1) ? 25 : 15);
    }
}

// Pre-permute 26 filter spectra (24 psi + phi + phi) into digit-reversed order.
__global__ void filt_prep_kernel(const float* __restrict__ psi,
                                 const float* __restrict__ phi) {
    int p = blockIdx.x * blockDim.x + threadIdx.x;
    int row = p >> 14;
    if (row >= 26) return;
    int q = p & (N_FFT - 1);
    int src = digitrev4(q);
    const float* f = (row < 24) ? (psi + (size_t)row * N_FFT * 2) : phi;
    g_filtrev[p] = make_float2(f[2 * src], f[2 * src + 1]);
}

// Forward: [gmem reflect-read + stages 0,1] -> phase<2> -> phase<4> ->
// [stage 6 + gmem store]. Natural in -> digit-reversed out.
__global__ void __launch_bounds__(NT)
fwd_fft_kernel(const float* __restrict__ x) {
    extern __shared__ float2 sm[];
    const int seq = blockIdx.x;
    const float2* xi = (const float2*)(x + (size_t)seq * T_LEN * 2);
    const int tid = threadIdx.x;

    // Fused: reflection pad + stages 0,1 (L=4096,1024) directly from gmem.
    // Unit v reads indices v + m*1024 + q*4096; q=2,3 land in the reflected
    // half: pad[g] = x[16383-g]. All reads coalesced (q=2,3 reversed).
    {
        const int v = tid;
        float2 d[4][4];
#pragma unroll
        for (int m = 0; m < 4; m++) {
            int g0 = v + m * 1024;
            d[m][0] = xi[g0];
            d[m][1] = xi[g0 + 4096];
            d[m][2] = xi[8191 - g0];
            d[m][3] = xi[4095 - g0];
        }
#pragma unroll
        for (int m = 0; m < 4; m++)
            bfly4_dif(d[m][0], d[m][1], d[m][2], d[m][3], g_tw[v + m * 1024]);
        float2 w1b = g_tw[v << 2];
#pragma unroll
        for (int q = 0; q < 4; q++)
            bfly4_dif(d[0][q], d[1][q], d[2][q], d[3][q], w1b);
#pragma unroll
        for (int m = 0; m < 4; m++)
#pragma unroll
            for (int q = 0; q < 4; q++)
                sm[P(v + m * 1024 + q * 4096)] = d[m][q];
    }
    __syncthreads();

    fwd_fused_phase<2>(sm, tid);                // stages 2,3 (L=256,64)
    fwd_fused_phase<4>(sm, tid);                // stages 4,5 (L=16,4)

    // Fused final stage s=6 (L=1, twiddle-free) + coalesced gmem store.
    float4* out4 = (float4*)(g_xhat + (size_t)seq * N_FFT);
#pragma unroll
    for (int k = 0; k < 4; k++) {
        int base = 4 * (tid + k * NT);
        float2 a0 = sm[P(base)],     a1 = sm[P(base + 1)];
        float2 a2 = sm[P(base + 2)], a3 = sm[P(base + 3)];
        bfly4_dif_nw(a0, a1, a2, a3);
        out4[base >> 1]       = make_float4(a0.x, a0.y, a1.x, a1.y);
        out4[(base >> 1) + 1] = make_float4(a2.x, a2.y, a3.x, a3.y);
    }
}

// Inverse: [gmem gather*filter + stage 6] -> phase<4> -> phase<2> ->
// phase<0> -> write first T samples scaled by 1/N.
__global__ void __launch_bounds__(NT)
inv_fft_kernel(float* __restrict__ out) {
    extern __shared__ float2 sm[];
    const int b  = blockIdx.x;
    const int a  = b & 3;
    const int cj = (b >> 2) & 31;
    const int c  = b >> 7;
    const int jr = g_idx[2 * cj];
    const int f  = g_idx[2 * cj + 1];
    const float4* xh4 = (const float4*)(g_xhat +
                        (size_t)((c * 16 + jr) * 4 + a) * N_FFT);
    const float4* fr4 = (const float4*)(g_filtrev + (size_t)f * N_FFT);
    const int tid = threadIdx.x;

    // Fused: pointwise multiply + stage s=6 (L=1, twiddle-free) from gmem.
#pragma unroll
    for (int k = 0; k < 4; k++) {
        int base = 4 * (tid + k * NT);
        float4 xa = xh4[base >> 1], xb = xh4[(base >> 1) + 1];
        float4 fa = fr4[base >> 1], fb = fr4[(base >> 1) + 1];
        float2 a0 = cmul(make_float2(xa.x, xa.y), make_float2(fa.x, fa.y));
        float2 a1 = cmul(make_float2(xa.z, xa.w), make_float2(fa.z, fa.w));
        float2 a2 = cmul(make_float2(xb.x, xb.y), make_float2(fb.x, fb.y));
        float2 a3 = cmul(make_float2(xb.z, xb.w), make_float2(fb.z, fb.w));
        bfly4_dit_nw(a0, a1, a2, a3);
        sm[P(base)] = a0;     sm[P(base + 1)] = a1;
        sm[P(base + 2)] = a2; sm[P(base + 3)] = a3;
    }
    __syncthreads();

    inv_fused_phase<4>(sm, tid);                // stages 5,4
    inv_fused_phase<2>(sm, tid);                // stages 3,2
    inv_fused_phase<0>(sm, tid);                // stages 1,0

    float2* o = (float2*)(out + (size_t)b * T_LEN * 2);
    const float scale = 1.0f / (float)N_FFT;
#pragma unroll
    for (int k = 0; k < T_LEN / NT; k++) {
        int t = tid + k * NT;
        float2 v = sm[P(t)];
        o[t] = make_float2(v.x * scale, v.y * scale);
    }
}

extern "C" void kernel_launch(void* const* d_in, const int* in_sizes, int n_in,
                              void* d_out, int out_size) {
    const float* x   = (const float*)d_in[0];
    const float* psi = (const float*)d_in[1];
    const float* phi = (const float*)d_in[2];
    const int* idxr  = (const int*)d_in[3];
    float* out       = (float*)d_out;

    cudaFuncSetAttribute(fwd_fft_kernel,
                         cudaFuncAttributeMaxDynamicSharedMemorySize, SMEM_BYTES);
    cudaFuncSetAttribute(inv_fft_kernel,
                         cudaFuncAttributeMaxDynamicSharedMemorySize, SMEM_BYTES);

    tw_init_kernel<<<(N_FFT / 4 + 511) / 512, 512>>>();
    idx_norm_kernel<<<1, 64>>>(idxr);
    filt_prep_kernel<<<(26 * N_FFT + 511) / 512, 512>>>(psi, phi);
    fwd_fft_kernel<<<512, NT, SMEM_BYTES>>>(x);
    inv_fft_kernel<<<1024, NT, SMEM_BYTES>>>(out);
}